// round 5
// baseline (speedup 1.0000x reference)
#include <cuda_runtime.h>
#include <cstdint>

#define H 4
#define KCODES 8192
#define DFULL 1024
#define DHEAD 256
#define BATCH 8192

#define TILE_M 128
#define TILE_N 128
#define KC 16
#define NCHUNK (DHEAD / KC)   // 16
#define LDA 20                // padded smem stride (floats): conflict-free

// Scratch (device globals; no allocations allowed)
__device__ unsigned long long g_min[BATCH * H];
__device__ float g_e2[H * KCODES];
__device__ float g_xhi[BATCH * DFULL];
__device__ float g_xlo[BATCH * DFULL];
__device__ float g_chi[H * KCODES * DHEAD];
__device__ float g_clo[H * KCODES * DHEAD];

__device__ __forceinline__ float tf32_rn(float v) {
    uint32_t r;
    asm("cvt.rn.tf32.f32 %0, %1;" : "=r"(r) : "f"(v));
    return __uint_as_float(r);
}
__device__ __forceinline__ uint32_t float_key(float f) {
    unsigned ub = __float_as_uint(f);
    return (ub & 0x80000000u) ? ~ub : (ub | 0x80000000u);
}

#define MMA_TF32(c, a, b0, b1) \
    asm volatile("mma.sync.aligned.m16n8k8.row.col.f32.tf32.tf32.f32 " \
        "{%0,%1,%2,%3}, {%4,%5,%6,%7}, {%8,%9}, {%0,%1,%2,%3};" \
        : "+f"((c)[0]), "+f"((c)[1]), "+f"((c)[2]), "+f"((c)[3]) \
        : "r"((a)[0]), "r"((a)[1]), "r"((a)[2]), "r"((a)[3]), \
          "r"(b0), "r"(b1))

#define CP_ASYNC16(dst, src) \
    asm volatile("cp.async.cg.shared.global [%0], [%1], 16;" :: "r"(dst), "l"(src))
#define CP_COMMIT() asm volatile("cp.async.commit_group;" ::: "memory")
#define CP_WAIT(n)  asm volatile("cp.async.wait_group %0;" :: "n"(n) : "memory")

// ---------------------------------------------------------------------------
__global__ void reset_kernel() {
    int i = blockIdx.x * blockDim.x + threadIdx.x;
    if (i < BATCH * H) g_min[i] = 0xFFFFFFFFFFFFFFFFull;
}

__global__ void e2_kernel(const float* __restrict__ cb) {
    int warp = (blockIdx.x * blockDim.x + threadIdx.x) >> 5;
    int lane = threadIdx.x & 31;
    if (warp >= H * KCODES) return;
    const float* p = cb + (size_t)warp * DHEAD;
    float s = 0.f;
#pragma unroll
    for (int i = 0; i < DHEAD; i += 32) {
        float v = p[i + lane];
        s = fmaf(v, v, s);
    }
#pragma unroll
    for (int o = 16; o; o >>= 1) s += __shfl_xor_sync(0xFFFFFFFFu, s, o);
    if (lane == 0) g_e2[warp] = s;
}

// Pre-split src into tf32 hi + tf32-rounded residual lo
__global__ void split_kernel(const float* __restrict__ src,
                             float* __restrict__ hi, float* __restrict__ lo, int n4) {
    int i = blockIdx.x * blockDim.x + threadIdx.x;
    if (i >= n4) return;
    float4 v = ((const float4*)src)[i];
    float4 h, l;
    h.x = tf32_rn(v.x); l.x = tf32_rn(v.x - h.x);
    h.y = tf32_rn(v.y); l.y = tf32_rn(v.y - h.y);
    h.z = tf32_rn(v.z); l.z = tf32_rn(v.z - h.z);
    h.w = tf32_rn(v.w); l.w = tf32_rn(v.w - h.w);
    ((float4*)hi)[i] = h;
    ((float4*)lo)[i] = l;
}

// ---------------------------------------------------------------------------
// Split-precision TF32 mma.sync GEMM + fused argmin, cp.async double-buffered.
// grid (BATCH/128, KCODES/128, H), 256 threads (8 warps: 2 M x 4 N).
// ---------------------------------------------------------------------------
// Dynamic smem layout (floats):
//   buf b in {0,1}: Ah at b*10240, Al +2560, Bh +5120, Bl +7680
//   e2s at 20480 (128), red (ull) at 20608*4 bytes
#define SM_BUF(b)   ((b) * 10240)
#define SM_E2       20480
#define SM_RED_B    (20608 * 4)
#define SMEM_TOTAL  (20608 * 4 + TILE_M * 4 * 8)   // 86528 B

__device__ __forceinline__ void copy_chunk(
    uint32_t s0, const float* __restrict__ xh, const float* __restrict__ xl,
    const float* __restrict__ eh, const float* __restrict__ el, int ck, int tid) {
#pragma unroll
    for (int i = 0; i < 2; i++) {
        int idx = tid + 256 * i;
        int r = idx >> 2, c4 = idx & 3;
        uint32_t off = (uint32_t)(r * LDA + c4 * 4) * 4u;
        size_t ga = (size_t)r * DFULL + ck * KC + c4 * 4;
        size_t gb = (size_t)r * DHEAD + ck * KC + c4 * 4;
        CP_ASYNC16(s0 + off,                 xh + ga);
        CP_ASYNC16(s0 + 2560 * 4 + off,      xl + ga);
        CP_ASYNC16(s0 + 5120 * 4 + off,      eh + gb);
        CP_ASYNC16(s0 + 7680 * 4 + off,      el + gb);
    }
}

__global__ __launch_bounds__(256, 2)
void dist_argmin_kernel() {
    extern __shared__ float smf[];
    unsigned long long* red = (unsigned long long*)((char*)smf + SM_RED_B);
    float* e2s = smf + SM_E2;

    const int tid = threadIdx.x;
    const int lane = tid & 31;
    const int wid = tid >> 5;
    const int warp_m = wid & 1;
    const int warp_n = wid >> 1;
    const int g  = lane >> 2;
    const int t4 = lane & 3;

    const int h  = blockIdx.z;
    const int bi = blockIdx.x * TILE_M;
    const int kj = blockIdx.y * TILE_N;

    if (tid < TILE_N) e2s[tid] = g_e2[h * KCODES + kj + tid];

    const float* xh = g_xhi + (size_t)bi * DFULL + (size_t)h * DHEAD;
    const float* xl = g_xlo + (size_t)bi * DFULL + (size_t)h * DHEAD;
    const float* eh = g_chi + ((size_t)h * KCODES + kj) * DHEAD;
    const float* el = g_clo + ((size_t)h * KCODES + kj) * DHEAD;

    uint32_t sbase = (uint32_t)__cvta_generic_to_shared(smf);

    float acc[4][4][4];
#pragma unroll
    for (int mt = 0; mt < 4; mt++)
#pragma unroll
        for (int nt = 0; nt < 4; nt++)
#pragma unroll
            for (int r = 0; r < 4; r++) acc[mt][nt][r] = 0.f;

    // prologue: chunk 0 into buffer 0
    copy_chunk(sbase + SM_BUF(0) * 4, xh, xl, eh, el, 0, tid);
    CP_COMMIT();

#pragma unroll 1
    for (int ck = 0; ck < NCHUNK; ck++) {
        if (ck + 1 < NCHUNK) {
            copy_chunk(sbase + SM_BUF((ck + 1) & 1) * 4, xh, xl, eh, el, ck + 1, tid);
            CP_COMMIT();
            CP_WAIT(1);       // chunk ck complete; ck+1 may be in flight
        } else {
            CP_WAIT(0);
        }
        __syncthreads();

        const float* Ah = smf + SM_BUF(ck & 1);
        const float* Al = Ah + 2560;
        const float* Bh = Ah + 5120;
        const float* Bl = Ah + 7680;

#pragma unroll
        for (int ks = 0; ks < 2; ks++) {
            const int k0 = ks * 8;
            uint32_t ah[4][4], al[4][4];
#pragma unroll
            for (int mt = 0; mt < 4; mt++) {
                int m0 = (warp_m * 64 + mt * 16 + g) * LDA + k0 + t4;
                int m1 = m0 + 8 * LDA;
                ah[mt][0] = __float_as_uint(Ah[m0]);
                ah[mt][1] = __float_as_uint(Ah[m1]);
                ah[mt][2] = __float_as_uint(Ah[m0 + 4]);
                ah[mt][3] = __float_as_uint(Ah[m1 + 4]);
                al[mt][0] = __float_as_uint(Al[m0]);
                al[mt][1] = __float_as_uint(Al[m1]);
                al[mt][2] = __float_as_uint(Al[m0 + 4]);
                al[mt][3] = __float_as_uint(Al[m1 + 4]);
            }
#pragma unroll
            for (int nt = 0; nt < 4; nt++) {
                int n0 = (warp_n * 32 + nt * 8 + g) * LDA + k0 + t4;
                uint32_t bh0 = __float_as_uint(Bh[n0]);
                uint32_t bh1 = __float_as_uint(Bh[n0 + 4]);
                uint32_t bl0 = __float_as_uint(Bl[n0]);
                uint32_t bl1 = __float_as_uint(Bl[n0 + 4]);
#pragma unroll
                for (int mt = 0; mt < 4; mt++) {
                    MMA_TF32(acc[mt][nt], ah[mt], bh0, bh1);
                    MMA_TF32(acc[mt][nt], ah[mt], bl0, bl1);
                    MMA_TF32(acc[mt][nt], al[mt], bh0, bh1);
                }
            }
        }
        __syncthreads();
    }

    // ---- epilogue: dist = e2 - 2*acc; per-row packed argmin ----
#pragma unroll
    for (int mt = 0; mt < 4; mt++) {
        int r0 = warp_m * 64 + mt * 16 + g;
        int r1 = r0 + 8;
        unsigned long long b0 = 0xFFFFFFFFFFFFFFFFull;
        unsigned long long b1 = 0xFFFFFFFFFFFFFFFFull;
#pragma unroll
        for (int nt = 0; nt < 4; nt++) {
            int c0 = warp_n * 32 + nt * 8 + 2 * t4;
            float d00 = fmaf(-2.f, acc[mt][nt][0], e2s[c0]);
            float d01 = fmaf(-2.f, acc[mt][nt][1], e2s[c0 + 1]);
            float d10 = fmaf(-2.f, acc[mt][nt][2], e2s[c0]);
            float d11 = fmaf(-2.f, acc[mt][nt][3], e2s[c0 + 1]);
            unsigned long long k00 = ((unsigned long long)float_key(d00) << 32) | (unsigned)(kj + c0);
            unsigned long long k01 = ((unsigned long long)float_key(d01) << 32) | (unsigned)(kj + c0 + 1);
            unsigned long long k10 = ((unsigned long long)float_key(d10) << 32) | (unsigned)(kj + c0);
            unsigned long long k11 = ((unsigned long long)float_key(d11) << 32) | (unsigned)(kj + c0 + 1);
            b0 = (k00 < b0) ? k00 : b0;  b0 = (k01 < b0) ? k01 : b0;
            b1 = (k10 < b1) ? k10 : b1;  b1 = (k11 < b1) ? k11 : b1;
        }
        unsigned long long o;
        o = __shfl_xor_sync(0xFFFFFFFFu, b0, 1); b0 = (o < b0) ? o : b0;
        o = __shfl_xor_sync(0xFFFFFFFFu, b0, 2); b0 = (o < b0) ? o : b0;
        o = __shfl_xor_sync(0xFFFFFFFFu, b1, 1); b1 = (o < b1) ? o : b1;
        o = __shfl_xor_sync(0xFFFFFFFFu, b1, 2); b1 = (o < b1) ? o : b1;
        if (t4 == 0) {
            red[r0 * 4 + warp_n] = b0;
            red[r1 * 4 + warp_n] = b1;
        }
    }
    __syncthreads();

    if (tid < TILE_M) {
        unsigned long long best = red[tid * 4];
#pragma unroll
        for (int i = 1; i < 4; i++) {
            unsigned long long v = red[tid * 4 + i];
            best = (v < best) ? v : best;
        }
        atomicMin(&g_min[(size_t)(bi + tid) * H + h], best);
    }
}

// ---------------------------------------------------------------------------
__global__ void finalize_kernel(const float* __restrict__ x, const float* __restrict__ cb,
                                float* __restrict__ loss, float* __restrict__ quant,
                                float* __restrict__ codes_out) {
    const int b = blockIdx.x;
    const int tid = threadIdx.x;
    __shared__ float sred[256];

    float partial = 0.f;
#pragma unroll
    for (int h = 0; h < H; h++) {
        unsigned long long packed = g_min[(size_t)b * H + h];
        unsigned code = (unsigned)(packed & 0xFFFFFFFFu);
        if (tid == 0) codes_out[(size_t)b * H + h] = (float)code;
        float qv = cb[((size_t)h * KCODES + code) * DHEAD + tid];
        float xv = x[(size_t)b * DFULL + (size_t)h * DHEAD + tid];
        quant[(size_t)b * DFULL + (size_t)h * DHEAD + tid] = qv;
        float d = qv - xv;
        partial = fmaf(d, d, partial);
    }
    sred[tid] = partial;
    __syncthreads();
#pragma unroll
    for (int s = 128; s > 0; s >>= 1) {
        if (tid < s) sred[tid] += sred[tid + s];
        __syncthreads();
    }
    if (tid == 0) loss[b] = 0.25f * sred[0] * (1.0f / (float)DHEAD);
}

// ---------------------------------------------------------------------------
extern "C" void kernel_launch(void* const* d_in, const int* in_sizes, int n_in,
                              void* d_out, int out_size) {
    const float* x  = (const float*)d_in[0];
    const float* cb = (const float*)d_in[1];
    float* out = (float*)d_out;

    float* loss  = out;
    float* quant = out + BATCH;
    float* codes = out + BATCH + (size_t)BATCH * DFULL;

    cudaFuncSetAttribute(dist_argmin_kernel,
                         cudaFuncAttributeMaxDynamicSharedMemorySize, SMEM_TOTAL);

    float *xhi, *xlo, *chi, *clo;
    cudaGetSymbolAddress((void**)&xhi, g_xhi);
    cudaGetSymbolAddress((void**)&xlo, g_xlo);
    cudaGetSymbolAddress((void**)&chi, g_chi);
    cudaGetSymbolAddress((void**)&clo, g_clo);

    reset_kernel<<<(BATCH * H + 255) / 256, 256>>>();
    e2_kernel<<<(H * KCODES) / 8, 256>>>(cb);

    const int n4 = BATCH * DFULL / 4;   // same count for cb
    split_kernel<<<(n4 + 255) / 256, 256>>>(x, xhi, xlo, n4);
    split_kernel<<<(n4 + 255) / 256, 256>>>(cb, chi, clo, n4);

    dim3 grid(BATCH / TILE_M, KCODES / TILE_N, H);
    dist_argmin_kernel<<<grid, 256, SMEM_TOTAL>>>();

    finalize_kernel<<<BATCH, 256>>>(x, cb, loss, quant, codes);
}

// round 6
// speedup vs baseline: 1.5138x; 1.5138x over previous
#include <cuda_runtime.h>
#include <cstdint>

#define H 4
#define KCODES 8192
#define DFULL 1024
#define DHEAD 256
#define BATCH 8192

#define TILE_M 128
#define TILE_N 128
#define KC 16
#define NCHUNK (DHEAD / KC)   // 16
#define LDA 20                // padded smem stride (floats)
#define MARGIN 2.0f

// Scratch (device globals; no allocations allowed)
__device__ float g_e2[H * KCODES];
__device__ float g_dist[(size_t)BATCH * H * KCODES];   // 1 GB approx distances
__device__ unsigned g_code[BATCH * H];

__device__ __forceinline__ uint32_t float_key(float f) {
    unsigned ub = __float_as_uint(f);
    return (ub & 0x80000000u) ? ~ub : (ub | 0x80000000u);
}

#define MMA_TF32(c, a, b0, b1) \
    asm volatile("mma.sync.aligned.m16n8k8.row.col.f32.tf32.tf32.f32 " \
        "{%0,%1,%2,%3}, {%4,%5,%6,%7}, {%8,%9}, {%0,%1,%2,%3};" \
        : "+f"((c)[0]), "+f"((c)[1]), "+f"((c)[2]), "+f"((c)[3]) \
        : "r"((a)[0]), "r"((a)[1]), "r"((a)[2]), "r"((a)[3]), \
          "r"(b0), "r"(b1))

#define CP_ASYNC16(dst, src) \
    asm volatile("cp.async.cg.shared.global [%0], [%1], 16;" :: "r"(dst), "l"(src))
#define CP_COMMIT() asm volatile("cp.async.commit_group;" ::: "memory")
#define CP_WAIT(n)  asm volatile("cp.async.wait_group %0;" :: "n"(n) : "memory")

// ---------------------------------------------------------------------------
__global__ void e2_kernel(const float* __restrict__ cb) {
    int warp = (blockIdx.x * blockDim.x + threadIdx.x) >> 5;
    int lane = threadIdx.x & 31;
    if (warp >= H * KCODES) return;
    const float* p = cb + (size_t)warp * DHEAD;
    float s = 0.f;
#pragma unroll
    for (int i = 0; i < DHEAD; i += 32) {
        float v = p[i + lane];
        s = fmaf(v, v, s);
    }
#pragma unroll
    for (int o = 16; o; o >>= 1) s += __shfl_xor_sync(0xFFFFFFFFu, s, o);
    if (lane == 0) g_e2[warp] = s;
}

// ---------------------------------------------------------------------------
// 1-pass TF32 GEMM (raw fp32 operands, HW truncation) storing approx dists.
// grid (BATCH/128, KCODES/128, H), 256 threads (8 warps: 2 M x 4 N).
// ---------------------------------------------------------------------------
__global__ __launch_bounds__(256, 2)
void dist_kernel(const float* __restrict__ x, const float* __restrict__ cb) {
    __shared__ float As[2][2560];   // 128 rows x LDA
    __shared__ float Bs[2][2560];
    __shared__ float e2s[TILE_N];

    const int tid = threadIdx.x;
    const int lane = tid & 31;
    const int wid = tid >> 5;
    const int warp_m = wid & 1;
    const int warp_n = wid >> 1;
    const int g  = lane >> 2;
    const int t4 = lane & 3;

    const int h  = blockIdx.z;
    const int bi = blockIdx.x * TILE_M;
    const int kj = blockIdx.y * TILE_N;

    if (tid < TILE_N) e2s[tid] = g_e2[h * KCODES + kj + tid];

    const float* xg = x  + (size_t)bi * DFULL + (size_t)h * DHEAD;
    const float* eg = cb + ((size_t)h * KCODES + kj) * DHEAD;

    const uint32_t sA0 = (uint32_t)__cvta_generic_to_shared(&As[0][0]);
    const uint32_t sA1 = (uint32_t)__cvta_generic_to_shared(&As[1][0]);
    const uint32_t sB0 = (uint32_t)__cvta_generic_to_shared(&Bs[0][0]);
    const uint32_t sB1 = (uint32_t)__cvta_generic_to_shared(&Bs[1][0]);

    float acc[4][4][4];
#pragma unroll
    for (int mt = 0; mt < 4; mt++)
#pragma unroll
        for (int nt = 0; nt < 4; nt++)
#pragma unroll
            for (int r = 0; r < 4; r++) acc[mt][nt][r] = 0.f;

    // copy helper inline: chunk ck into buffer b
    const int r0c = tid >> 2, c4c = tid & 3;               // 2 rows per thread
#define COPY_CHUNK(sa, sb, ck) do { \
        uint32_t off0 = (uint32_t)(r0c * LDA + c4c * 4) * 4u; \
        uint32_t off1 = (uint32_t)((r0c + 64) * LDA + c4c * 4) * 4u; \
        size_t ga0 = (size_t)r0c * DFULL + (ck) * KC + c4c * 4; \
        size_t ga1 = (size_t)(r0c + 64) * DFULL + (ck) * KC + c4c * 4; \
        size_t gb0 = (size_t)r0c * DHEAD + (ck) * KC + c4c * 4; \
        size_t gb1 = (size_t)(r0c + 64) * DHEAD + (ck) * KC + c4c * 4; \
        CP_ASYNC16((sa) + off0, xg + ga0); \
        CP_ASYNC16((sa) + off1, xg + ga1); \
        CP_ASYNC16((sb) + off0, eg + gb0); \
        CP_ASYNC16((sb) + off1, eg + gb1); \
    } while (0)

    COPY_CHUNK(sA0, sB0, 0);
    CP_COMMIT();

#pragma unroll 1
    for (int ck = 0; ck < NCHUNK; ck++) {
        if (ck + 1 < NCHUNK) {
            if ((ck + 1) & 1) COPY_CHUNK(sA1, sB1, ck + 1);
            else              COPY_CHUNK(sA0, sB0, ck + 1);
            CP_COMMIT();
            CP_WAIT(1);
        } else {
            CP_WAIT(0);
        }
        __syncthreads();

        const float* Ah = As[ck & 1];
        const float* Bh = Bs[ck & 1];

#pragma unroll
        for (int ks = 0; ks < 2; ks++) {
            const int k0 = ks * 8;
            uint32_t ah[4][4];
#pragma unroll
            for (int mt = 0; mt < 4; mt++) {
                int m0 = (warp_m * 64 + mt * 16 + g) * LDA + k0 + t4;
                int m1 = m0 + 8 * LDA;
                ah[mt][0] = __float_as_uint(Ah[m0]);
                ah[mt][1] = __float_as_uint(Ah[m1]);
                ah[mt][2] = __float_as_uint(Ah[m0 + 4]);
                ah[mt][3] = __float_as_uint(Ah[m1 + 4]);
            }
#pragma unroll
            for (int nt = 0; nt < 4; nt++) {
                int n0 = (warp_n * 32 + nt * 8 + g) * LDA + k0 + t4;
                uint32_t bh0 = __float_as_uint(Bh[n0]);
                uint32_t bh1 = __float_as_uint(Bh[n0 + 4]);
#pragma unroll
                for (int mt = 0; mt < 4; mt++)
                    MMA_TF32(acc[mt][nt], ah[mt], bh0, bh1);
            }
        }
        __syncthreads();
    }

    // ---- epilogue: store dist = e2 - 2*acc ----
#pragma unroll
    for (int mt = 0; mt < 4; mt++) {
        int r0 = warp_m * 64 + mt * 16 + g;
        int r1 = r0 + 8;
        size_t base0 = ((size_t)(bi + r0) * H + h) * KCODES + kj;
        size_t base1 = ((size_t)(bi + r1) * H + h) * KCODES + kj;
#pragma unroll
        for (int nt = 0; nt < 4; nt++) {
            int c0 = warp_n * 32 + nt * 8 + 2 * t4;
            float2 v0, v1;
            v0.x = fmaf(-2.f, acc[mt][nt][0], e2s[c0]);
            v0.y = fmaf(-2.f, acc[mt][nt][1], e2s[c0 + 1]);
            v1.x = fmaf(-2.f, acc[mt][nt][2], e2s[c0]);
            v1.y = fmaf(-2.f, acc[mt][nt][3], e2s[c0 + 1]);
            *(float2*)&g_dist[base0 + c0] = v0;
            *(float2*)&g_dist[base1 + c0] = v1;
        }
    }
}

// ---------------------------------------------------------------------------
// Re-rank: per (b,h), scan approx dists, exact-fp32 re-rank of candidates.
// ---------------------------------------------------------------------------
__global__ __launch_bounds__(256)
void rerank_kernel(const float* __restrict__ x, const float* __restrict__ cb) {
    const int bh = blockIdx.x;
    const int b = bh >> 2;     // H = 4
    const int h = bh & 3;
    const int tid = threadIdx.x;

    __shared__ float xs[DHEAD];
    __shared__ float smin[256];
    __shared__ unsigned long long best;

    if (tid == 0) best = 0xFFFFFFFFFFFFFFFFull;
    xs[tid] = x[(size_t)b * DFULL + h * DHEAD + tid];

    const float4* dist4 = (const float4*)(g_dist + (size_t)bh * KCODES);
    float4 v[8];
    float lmin = 3.4e38f;
#pragma unroll
    for (int i = 0; i < 8; i++) {
        v[i] = dist4[tid + 256 * i];
        lmin = fminf(lmin, fminf(fminf(v[i].x, v[i].y), fminf(v[i].z, v[i].w)));
    }
    smin[tid] = lmin;
    __syncthreads();
#pragma unroll
    for (int s = 128; s > 0; s >>= 1) {
        if (tid < s) smin[tid] = fminf(smin[tid], smin[tid + s]);
        __syncthreads();
    }
    const float thr = smin[0] + MARGIN;

#pragma unroll
    for (int i = 0; i < 8; i++) {
        float dv[4] = {v[i].x, v[i].y, v[i].z, v[i].w};
#pragma unroll
        for (int j = 0; j < 4; j++) {
            if (dv[j] <= thr) {
                int code = (tid + 256 * i) * 4 + j;
                const float* e = cb + ((size_t)h * KCODES + code) * DHEAD;
                float s0 = 0.f, s1 = 0.f, s2 = 0.f, s3 = 0.f;
#pragma unroll 8
                for (int d = 0; d < DHEAD; d += 4) {
                    s0 = fmaf(xs[d + 0], e[d + 0], s0);
                    s1 = fmaf(xs[d + 1], e[d + 1], s1);
                    s2 = fmaf(xs[d + 2], e[d + 2], s2);
                    s3 = fmaf(xs[d + 3], e[d + 3], s3);
                }
                float dot = (s0 + s1) + (s2 + s3);
                float de = fmaf(-2.f, dot, g_e2[h * KCODES + code]);
                unsigned long long key =
                    ((unsigned long long)float_key(de) << 32) | (unsigned)code;
                atomicMin(&best, key);
            }
        }
    }
    __syncthreads();
    if (tid == 0) g_code[bh] = (unsigned)(best & 0xFFFFFFFFu);
}

// ---------------------------------------------------------------------------
__global__ void finalize_kernel(const float* __restrict__ x, const float* __restrict__ cb,
                                float* __restrict__ loss, float* __restrict__ quant,
                                float* __restrict__ codes_out) {
    const int b = blockIdx.x;
    const int tid = threadIdx.x;
    __shared__ float sred[256];

    float partial = 0.f;
#pragma unroll
    for (int h = 0; h < H; h++) {
        unsigned code = g_code[b * H + h];
        if (tid == 0) codes_out[(size_t)b * H + h] = (float)code;
        float qv = cb[((size_t)h * KCODES + code) * DHEAD + tid];
        float xv = x[(size_t)b * DFULL + (size_t)h * DHEAD + tid];
        quant[(size_t)b * DFULL + (size_t)h * DHEAD + tid] = qv;
        float d = qv - xv;
        partial = fmaf(d, d, partial);
    }
    sred[tid] = partial;
    __syncthreads();
#pragma unroll
    for (int s = 128; s > 0; s >>= 1) {
        if (tid < s) sred[tid] += sred[tid + s];
        __syncthreads();
    }
    if (tid == 0) loss[b] = 0.25f * sred[0] * (1.0f / (float)DHEAD);
}

// ---------------------------------------------------------------------------
extern "C" void kernel_launch(void* const* d_in, const int* in_sizes, int n_in,
                              void* d_out, int out_size) {
    const float* x  = (const float*)d_in[0];
    const float* cb = (const float*)d_in[1];
    float* out = (float*)d_out;

    float* loss  = out;
    float* quant = out + BATCH;
    float* codes = out + BATCH + (size_t)BATCH * DFULL;

    e2_kernel<<<(H * KCODES) / 8, 256>>>(cb);

    dim3 grid(BATCH / TILE_M, KCODES / TILE_N, H);
    dist_kernel<<<grid, 256>>>(x, cb);

    rerank_kernel<<<BATCH * H, 256>>>(x, cb);

    finalize_kernel<<<BATCH, 256>>>(x, cb, loss, quant, codes);
}

// round 7
// speedup vs baseline: 1.8972x; 1.2533x over previous
#include <cuda_runtime.h>
#include <cuda_bf16.h>
#include <cuda_fp16.h>
#include <cstdint>

#define H 4
#define KCODES 8192
#define DFULL 1024
#define DHEAD 256
#define BATCH 8192

#define TILE_M 128
#define TILE_N 128
#define KC 32                  // bf16 elements per chunk
#define NCHUNK (DHEAD / KC)    // 8
#define LD2 40                 // smem row stride in halves (32 + 8 pad)
#define MARGIN 4.0f

// Scratch (device globals; no allocations allowed)
__device__ float g_e2[H * KCODES];
__device__ __nv_bfloat16 g_xb[(size_t)BATCH * DFULL];
__device__ __nv_bfloat16 g_cbb[(size_t)H * KCODES * DHEAD];
__device__ __half g_distH[(size_t)BATCH * H * KCODES];   // 512 MB approx dists
__device__ unsigned g_code[BATCH * H];

__device__ __forceinline__ uint32_t float_key(float f) {
    unsigned ub = __float_as_uint(f);
    return (ub & 0x80000000u) ? ~ub : (ub | 0x80000000u);
}

#define MMA_BF16(c, a, b0, b1) \
    asm volatile("mma.sync.aligned.m16n8k16.row.col.f32.bf16.bf16.f32 " \
        "{%0,%1,%2,%3}, {%4,%5,%6,%7}, {%8,%9}, {%0,%1,%2,%3};" \
        : "+f"((c)[0]), "+f"((c)[1]), "+f"((c)[2]), "+f"((c)[3]) \
        : "r"((a)[0]), "r"((a)[1]), "r"((a)[2]), "r"((a)[3]), \
          "r"(b0), "r"(b1))

#define CP_ASYNC16(dst, src) \
    asm volatile("cp.async.cg.shared.global [%0], [%1], 16;" :: "r"(dst), "l"(src))
#define CP_COMMIT() asm volatile("cp.async.commit_group;" ::: "memory")
#define CP_WAIT(n)  asm volatile("cp.async.wait_group %0;" :: "n"(n) : "memory")

// ---------------------------------------------------------------------------
__global__ void e2_kernel(const float* __restrict__ cb) {
    int warp = (blockIdx.x * blockDim.x + threadIdx.x) >> 5;
    int lane = threadIdx.x & 31;
    if (warp >= H * KCODES) return;
    const float* p = cb + (size_t)warp * DHEAD;
    float s = 0.f;
#pragma unroll
    for (int i = 0; i < DHEAD; i += 32) {
        float v = p[i + lane];
        s = fmaf(v, v, s);
    }
#pragma unroll
    for (int o = 16; o; o >>= 1) s += __shfl_xor_sync(0xFFFFFFFFu, s, o);
    if (lane == 0) g_e2[warp] = s;
}

// fp32 -> bf16 conversion (8 floats per thread)
__global__ void cvt_kernel(const float* __restrict__ src, __nv_bfloat16* __restrict__ dst, int n8) {
    int i = blockIdx.x * blockDim.x + threadIdx.x;
    if (i >= n8) return;
    float4 a = ((const float4*)src)[2 * i];
    float4 b = ((const float4*)src)[2 * i + 1];
    __nv_bfloat162 o[4];
    o[0] = __nv_bfloat162(__float2bfloat16_rn(a.x), __float2bfloat16_rn(a.y));
    o[1] = __nv_bfloat162(__float2bfloat16_rn(a.z), __float2bfloat16_rn(a.w));
    o[2] = __nv_bfloat162(__float2bfloat16_rn(b.x), __float2bfloat16_rn(b.y));
    o[3] = __nv_bfloat162(__float2bfloat16_rn(b.z), __float2bfloat16_rn(b.w));
    ((uint4*)dst)[i] = *(uint4*)o;
}

// ---------------------------------------------------------------------------
// 1-pass BF16 GEMM storing approx dists as fp16.
// grid (BATCH/128, KCODES/128, H), 256 threads (8 warps: 2 M x 4 N).
// ---------------------------------------------------------------------------
__global__ __launch_bounds__(256, 2)
void dist_kernel() {
    __shared__ __half As[2][TILE_M * LD2];   // stored as raw 16-bit (bf16 bits)
    __shared__ __half Bs[2][TILE_N * LD2];
    __shared__ float e2s[TILE_N];

    const int tid = threadIdx.x;
    const int lane = tid & 31;
    const int wid = tid >> 5;
    const int warp_m = wid & 1;
    const int warp_n = wid >> 1;
    const int g  = lane >> 2;
    const int t4 = lane & 3;

    const int h  = blockIdx.z;
    const int bi = blockIdx.x * TILE_M;
    const int kj = blockIdx.y * TILE_N;

    if (tid < TILE_N) e2s[tid] = g_e2[h * KCODES + kj + tid];

    const __nv_bfloat16* xg = g_xb  + (size_t)bi * DFULL + (size_t)h * DHEAD;
    const __nv_bfloat16* eg = g_cbb + ((size_t)h * KCODES + kj) * DHEAD;

    const uint32_t sA[2] = {
        (uint32_t)__cvta_generic_to_shared(&As[0][0]),
        (uint32_t)__cvta_generic_to_shared(&As[1][0])};
    const uint32_t sB[2] = {
        (uint32_t)__cvta_generic_to_shared(&Bs[0][0]),
        (uint32_t)__cvta_generic_to_shared(&Bs[1][0])};

    float acc[4][4][4];
#pragma unroll
    for (int mt = 0; mt < 4; mt++)
#pragma unroll
        for (int nt = 0; nt < 4; nt++)
#pragma unroll
            for (int r = 0; r < 4; r++) acc[mt][nt][r] = 0.f;

    // copy: per chunk each thread does 2 A + 2 B 16-byte cp.async
#define COPY_CHUNK(buf, ck) do { \
        _Pragma("unroll") \
        for (int i = 0; i < 2; i++) { \
            int idx = tid + 256 * i; \
            int r = idx >> 2, s8 = idx & 3; \
            uint32_t off = (uint32_t)(r * LD2 + s8 * 8) * 2u; \
            CP_ASYNC16(sA[buf] + off, xg + (size_t)r * DFULL + (ck) * KC + s8 * 8); \
            CP_ASYNC16(sB[buf] + off, eg + (size_t)r * DHEAD + (ck) * KC + s8 * 8); \
        } \
    } while (0)

    COPY_CHUNK(0, 0);
    CP_COMMIT();

#pragma unroll 1
    for (int ck = 0; ck < NCHUNK; ck++) {
        if (ck + 1 < NCHUNK) {
            COPY_CHUNK((ck + 1) & 1, ck + 1);
            CP_COMMIT();
            CP_WAIT(1);
        } else {
            CP_WAIT(0);
        }
        __syncthreads();

        const __half* Ah = As[ck & 1];
        const __half* Bh = Bs[ck & 1];

#pragma unroll
        for (int ks = 0; ks < 2; ks++) {
            const int k0 = ks * 16;
            uint32_t a[4][4];
#pragma unroll
            for (int mt = 0; mt < 4; mt++) {
                int r0 = (warp_m * 64 + mt * 16 + g) * LD2 + k0 + 2 * t4;
                int r1 = r0 + 8 * LD2;
                a[mt][0] = *(const uint32_t*)&Ah[r0];
                a[mt][1] = *(const uint32_t*)&Ah[r1];
                a[mt][2] = *(const uint32_t*)&Ah[r0 + 8];
                a[mt][3] = *(const uint32_t*)&Ah[r1 + 8];
            }
#pragma unroll
            for (int nt = 0; nt < 4; nt++) {
                int n0 = (warp_n * 32 + nt * 8 + g) * LD2 + k0 + 2 * t4;
                uint32_t b0 = *(const uint32_t*)&Bh[n0];
                uint32_t b1 = *(const uint32_t*)&Bh[n0 + 8];
#pragma unroll
                for (int mt = 0; mt < 4; mt++)
                    MMA_BF16(acc[mt][nt], a[mt], b0, b1);
            }
        }
        __syncthreads();
    }

    // ---- epilogue: dist = e2 - 2*acc, store as fp16 pairs ----
#pragma unroll
    for (int mt = 0; mt < 4; mt++) {
        int r0 = warp_m * 64 + mt * 16 + g;
        int r1 = r0 + 8;
        size_t base0 = ((size_t)(bi + r0) * H + h) * KCODES + kj;
        size_t base1 = ((size_t)(bi + r1) * H + h) * KCODES + kj;
#pragma unroll
        for (int nt = 0; nt < 4; nt++) {
            int c0 = warp_n * 32 + nt * 8 + 2 * t4;
            __half2 v0 = __floats2half2_rn(
                fmaf(-2.f, acc[mt][nt][0], e2s[c0]),
                fmaf(-2.f, acc[mt][nt][1], e2s[c0 + 1]));
            __half2 v1 = __floats2half2_rn(
                fmaf(-2.f, acc[mt][nt][2], e2s[c0]),
                fmaf(-2.f, acc[mt][nt][3], e2s[c0 + 1]));
            *(__half2*)&g_distH[base0 + c0] = v0;
            *(__half2*)&g_distH[base1 + c0] = v1;
        }
    }
}

// ---------------------------------------------------------------------------
// Re-rank: per (b,h), scan fp16 approx dists, exact fp32 re-rank of candidates.
// ---------------------------------------------------------------------------
__global__ __launch_bounds__(256)
void rerank_kernel(const float* __restrict__ x, const float* __restrict__ cb) {
    const int bh = blockIdx.x;
    const int b = bh >> 2;     // H = 4
    const int h = bh & 3;
    const int tid = threadIdx.x;

    __shared__ float xs[DHEAD];
    __shared__ float smin[256];
    __shared__ unsigned long long best;

    if (tid == 0) best = 0xFFFFFFFFFFFFFFFFull;
    xs[tid] = x[(size_t)b * DFULL + h * DHEAD + tid];

    const uint4* d16 = (const uint4*)(g_distH + (size_t)bh * KCODES);
    uint4 raw[4];
    float lmin = 3.4e38f;
#pragma unroll
    for (int j = 0; j < 4; j++) {
        raw[j] = d16[tid + 256 * j];
        const __half2* hp = (const __half2*)&raw[j];
#pragma unroll
        for (int p = 0; p < 4; p++) {
            float2 f = __half22float2(hp[p]);
            lmin = fminf(lmin, fminf(f.x, f.y));
        }
    }
    smin[tid] = lmin;
    __syncthreads();
#pragma unroll
    for (int s = 128; s > 0; s >>= 1) {
        if (tid < s) smin[tid] = fminf(smin[tid], smin[tid + s]);
        __syncthreads();
    }
    const float thr = smin[0] + MARGIN;

#pragma unroll
    for (int j = 0; j < 4; j++) {
        const __half2* hp = (const __half2*)&raw[j];
#pragma unroll
        for (int p = 0; p < 4; p++) {
            float2 f = __half22float2(hp[p]);
#pragma unroll
            for (int q = 0; q < 2; q++) {
                float dv = (q == 0) ? f.x : f.y;
                if (dv <= thr) {
                    int code = (tid + 256 * j) * 8 + p * 2 + q;
                    const float* e = cb + ((size_t)h * KCODES + code) * DHEAD;
                    float s0 = 0.f, s1 = 0.f, s2 = 0.f, s3 = 0.f;
#pragma unroll 8
                    for (int d = 0; d < DHEAD; d += 4) {
                        s0 = fmaf(xs[d + 0], e[d + 0], s0);
                        s1 = fmaf(xs[d + 1], e[d + 1], s1);
                        s2 = fmaf(xs[d + 2], e[d + 2], s2);
                        s3 = fmaf(xs[d + 3], e[d + 3], s3);
                    }
                    float dot = (s0 + s1) + (s2 + s3);
                    float de = fmaf(-2.f, dot, g_e2[h * KCODES + code]);
                    unsigned long long key =
                        ((unsigned long long)float_key(de) << 32) | (unsigned)code;
                    atomicMin(&best, key);
                }
            }
        }
    }
    __syncthreads();
    if (tid == 0) g_code[bh] = (unsigned)(best & 0xFFFFFFFFu);
}

// ---------------------------------------------------------------------------
__global__ void finalize_kernel(const float* __restrict__ x, const float* __restrict__ cb,
                                float* __restrict__ loss, float* __restrict__ quant,
                                float* __restrict__ codes_out) {
    const int b = blockIdx.x;
    const int tid = threadIdx.x;
    __shared__ float sred[256];

    float partial = 0.f;
#pragma unroll
    for (int h = 0; h < H; h++) {
        unsigned code = g_code[b * H + h];
        if (tid == 0) codes_out[(size_t)b * H + h] = (float)code;
        float qv = cb[((size_t)h * KCODES + code) * DHEAD + tid];
        float xv = x[(size_t)b * DFULL + (size_t)h * DHEAD + tid];
        quant[(size_t)b * DFULL + (size_t)h * DHEAD + tid] = qv;
        float d = qv - xv;
        partial = fmaf(d, d, partial);
    }
    sred[tid] = partial;
    __syncthreads();
#pragma unroll
    for (int s = 128; s > 0; s >>= 1) {
        if (tid < s) sred[tid] += sred[tid + s];
        __syncthreads();
    }
    if (tid == 0) loss[b] = 0.25f * sred[0] * (1.0f / (float)DHEAD);
}

// ---------------------------------------------------------------------------
extern "C" void kernel_launch(void* const* d_in, const int* in_sizes, int n_in,
                              void* d_out, int out_size) {
    const float* x  = (const float*)d_in[0];
    const float* cb = (const float*)d_in[1];
    float* out = (float*)d_out;

    float* loss  = out;
    float* quant = out + BATCH;
    float* codes = out + BATCH + (size_t)BATCH * DFULL;

    __nv_bfloat16 *xb, *cbb;
    cudaGetSymbolAddress((void**)&xb, g_xb);
    cudaGetSymbolAddress((void**)&cbb, g_cbb);

    e2_kernel<<<(H * KCODES) / 8, 256>>>(cb);

    const int n8 = BATCH * DFULL / 8;   // same element count for cb
    cvt_kernel<<<(n8 + 255) / 256, 256>>>(x, xb, n8);
    cvt_kernel<<<(n8 + 255) / 256, 256>>>(cb, cbb, n8);

    dim3 grid(BATCH / TILE_M, KCODES / TILE_N, H);
    dist_kernel<<<grid, 256>>>();

    rerank_kernel<<<BATCH * H, 256>>>(x, cb);

    finalize_kernel<<<BATCH, 256>>>(x, cb, loss, quant, codes);
}

// round 8
// speedup vs baseline: 2.0614x; 1.0865x over previous
#include <cuda_runtime.h>
#include <cuda_bf16.h>
#include <cuda_fp16.h>
#include <cstdint>

#define H 4
#define KCODES 8192
#define DFULL 1024
#define DHEAD 256
#define BATCH 8192

#define TILE_M 128
#define TILE_N 128
#define NBLK (KCODES / TILE_N)   // 64 code-blocks per (b,h)
#define KC 32                    // bf16 elements per chunk
#define NCHUNK (DHEAD / KC)      // 8
#define LD2 40                   // smem row stride in halves
#define MARGIN 4.0f

// Scratch (device globals; no allocations allowed)
__device__ float g_e2[H * KCODES];
__device__ __nv_bfloat16 g_xb[(size_t)BATCH * DFULL];
__device__ __nv_bfloat16 g_cbb[(size_t)H * KCODES * DHEAD];
__device__ __half g_distH[(size_t)BATCH * H * KCODES];           // 512 MB approx dists
__device__ unsigned long long g_blkmin[(size_t)BATCH * H * NBLK]; // 16 MB per-block mins
__device__ unsigned g_code[BATCH * H];

__device__ __forceinline__ uint32_t float_key(float f) {
    unsigned ub = __float_as_uint(f);
    return (ub & 0x80000000u) ? ~ub : (ub | 0x80000000u);
}
__device__ __forceinline__ float key_float(uint32_t k) {
    unsigned ub = (k & 0x80000000u) ? (k & 0x7FFFFFFFu) : ~k;
    return __uint_as_float(ub);
}

#define MMA_BF16(c, a, b0, b1) \
    asm volatile("mma.sync.aligned.m16n8k16.row.col.f32.bf16.bf16.f32 " \
        "{%0,%1,%2,%3}, {%4,%5,%6,%7}, {%8,%9}, {%0,%1,%2,%3};" \
        : "+f"((c)[0]), "+f"((c)[1]), "+f"((c)[2]), "+f"((c)[3]) \
        : "r"((a)[0]), "r"((a)[1]), "r"((a)[2]), "r"((a)[3]), \
          "r"(b0), "r"(b1))

#define CP_ASYNC16(dst, src) \
    asm volatile("cp.async.cg.shared.global [%0], [%1], 16;" :: "r"(dst), "l"(src))
#define CP_COMMIT() asm volatile("cp.async.commit_group;" ::: "memory")
#define CP_WAIT(n)  asm volatile("cp.async.wait_group %0;" :: "n"(n) : "memory")

// ---------------------------------------------------------------------------
__global__ void e2_kernel(const float* __restrict__ cb) {
    int warp = (blockIdx.x * blockDim.x + threadIdx.x) >> 5;
    int lane = threadIdx.x & 31;
    if (warp >= H * KCODES) return;
    const float* p = cb + (size_t)warp * DHEAD;
    float s = 0.f;
#pragma unroll
    for (int i = 0; i < DHEAD; i += 32) {
        float v = p[i + lane];
        s = fmaf(v, v, s);
    }
#pragma unroll
    for (int o = 16; o; o >>= 1) s += __shfl_xor_sync(0xFFFFFFFFu, s, o);
    if (lane == 0) g_e2[warp] = s;
}

__global__ void cvt_kernel(const float* __restrict__ src, __nv_bfloat16* __restrict__ dst, int n8) {
    int i = blockIdx.x * blockDim.x + threadIdx.x;
    if (i >= n8) return;
    float4 a = ((const float4*)src)[2 * i];
    float4 b = ((const float4*)src)[2 * i + 1];
    __nv_bfloat162 o[4];
    o[0] = __nv_bfloat162(__float2bfloat16_rn(a.x), __float2bfloat16_rn(a.y));
    o[1] = __nv_bfloat162(__float2bfloat16_rn(a.z), __float2bfloat16_rn(a.w));
    o[2] = __nv_bfloat162(__float2bfloat16_rn(b.x), __float2bfloat16_rn(b.y));
    o[3] = __nv_bfloat162(__float2bfloat16_rn(b.z), __float2bfloat16_rn(b.w));
    ((uint4*)dst)[i] = *(uint4*)o;
}

// ---------------------------------------------------------------------------
// 1-pass BF16 GEMM storing fp16 dists + per-(row, block) packed mins.
// grid (BATCH/128, KCODES/128, H), 256 threads (8 warps: 2 M x 4 N).
// ---------------------------------------------------------------------------
__global__ __launch_bounds__(256, 2)
void dist_kernel() {
    __shared__ __half As[2][TILE_M * LD2];
    __shared__ __half Bs[2][TILE_N * LD2];
    __shared__ float e2s[TILE_N];
    __shared__ unsigned long long red[TILE_M][4];

    const int tid = threadIdx.x;
    const int lane = tid & 31;
    const int wid = tid >> 5;
    const int warp_m = wid & 1;
    const int warp_n = wid >> 1;
    const int g  = lane >> 2;
    const int t4 = lane & 3;

    const int h  = blockIdx.z;
    const int bi = blockIdx.x * TILE_M;
    const int kj = blockIdx.y * TILE_N;

    if (tid < TILE_N) e2s[tid] = g_e2[h * KCODES + kj + tid];

    const __nv_bfloat16* xg = g_xb  + (size_t)bi * DFULL + (size_t)h * DHEAD;
    const __nv_bfloat16* eg = g_cbb + ((size_t)h * KCODES + kj) * DHEAD;

    const uint32_t sA[2] = {
        (uint32_t)__cvta_generic_to_shared(&As[0][0]),
        (uint32_t)__cvta_generic_to_shared(&As[1][0])};
    const uint32_t sB[2] = {
        (uint32_t)__cvta_generic_to_shared(&Bs[0][0]),
        (uint32_t)__cvta_generic_to_shared(&Bs[1][0])};

    float acc[4][4][4];
#pragma unroll
    for (int mt = 0; mt < 4; mt++)
#pragma unroll
        for (int nt = 0; nt < 4; nt++)
#pragma unroll
            for (int r = 0; r < 4; r++) acc[mt][nt][r] = 0.f;

#define COPY_CHUNK(buf, ck) do { \
        _Pragma("unroll") \
        for (int i = 0; i < 2; i++) { \
            int idx = tid + 256 * i; \
            int r = idx >> 2, s8 = idx & 3; \
            uint32_t off = (uint32_t)(r * LD2 + s8 * 8) * 2u; \
            CP_ASYNC16(sA[buf] + off, xg + (size_t)r * DFULL + (ck) * KC + s8 * 8); \
            CP_ASYNC16(sB[buf] + off, eg + (size_t)r * DHEAD + (ck) * KC + s8 * 8); \
        } \
    } while (0)

    COPY_CHUNK(0, 0);
    CP_COMMIT();

#pragma unroll 1
    for (int ck = 0; ck < NCHUNK; ck++) {
        if (ck + 1 < NCHUNK) {
            COPY_CHUNK((ck + 1) & 1, ck + 1);
            CP_COMMIT();
            CP_WAIT(1);
        } else {
            CP_WAIT(0);
        }
        __syncthreads();

        const __half* Ah = As[ck & 1];
        const __half* Bh = Bs[ck & 1];

#pragma unroll
        for (int ks = 0; ks < 2; ks++) {
            const int k0 = ks * 16;
            uint32_t a[4][4];
#pragma unroll
            for (int mt = 0; mt < 4; mt++) {
                int r0 = (warp_m * 64 + mt * 16 + g) * LD2 + k0 + 2 * t4;
                int r1 = r0 + 8 * LD2;
                a[mt][0] = *(const uint32_t*)&Ah[r0];
                a[mt][1] = *(const uint32_t*)&Ah[r1];
                a[mt][2] = *(const uint32_t*)&Ah[r0 + 8];
                a[mt][3] = *(const uint32_t*)&Ah[r1 + 8];
            }
#pragma unroll
            for (int nt = 0; nt < 4; nt++) {
                int n0 = (warp_n * 32 + nt * 8 + g) * LD2 + k0 + 2 * t4;
                uint32_t b0 = *(const uint32_t*)&Bh[n0];
                uint32_t b1 = *(const uint32_t*)&Bh[n0 + 8];
#pragma unroll
                for (int mt = 0; mt < 4; mt++)
                    MMA_BF16(acc[mt][nt], a[mt], b0, b1);
            }
        }
        __syncthreads();
    }

    // ---- epilogue: dist = e2 - 2*acc; store fp16 + per-row block min ----
#pragma unroll
    for (int mt = 0; mt < 4; mt++) {
        int r0 = warp_m * 64 + mt * 16 + g;
        int r1 = r0 + 8;
        size_t base0 = ((size_t)(bi + r0) * H + h) * KCODES + kj;
        size_t base1 = ((size_t)(bi + r1) * H + h) * KCODES + kj;
        unsigned long long m0 = 0xFFFFFFFFFFFFFFFFull;
        unsigned long long m1 = 0xFFFFFFFFFFFFFFFFull;
#pragma unroll
        for (int nt = 0; nt < 4; nt++) {
            int c0 = warp_n * 32 + nt * 8 + 2 * t4;
            float d00 = fmaf(-2.f, acc[mt][nt][0], e2s[c0]);
            float d01 = fmaf(-2.f, acc[mt][nt][1], e2s[c0 + 1]);
            float d10 = fmaf(-2.f, acc[mt][nt][2], e2s[c0]);
            float d11 = fmaf(-2.f, acc[mt][nt][3], e2s[c0 + 1]);
            *(__half2*)&g_distH[base0 + c0] = __floats2half2_rn(d00, d01);
            *(__half2*)&g_distH[base1 + c0] = __floats2half2_rn(d10, d11);
            unsigned long long k00 = ((unsigned long long)float_key(d00) << 32) | (unsigned)(kj + c0);
            unsigned long long k01 = ((unsigned long long)float_key(d01) << 32) | (unsigned)(kj + c0 + 1);
            unsigned long long k10 = ((unsigned long long)float_key(d10) << 32) | (unsigned)(kj + c0);
            unsigned long long k11 = ((unsigned long long)float_key(d11) << 32) | (unsigned)(kj + c0 + 1);
            m0 = (k00 < m0) ? k00 : m0;  m0 = (k01 < m0) ? k01 : m0;
            m1 = (k10 < m1) ? k10 : m1;  m1 = (k11 < m1) ? k11 : m1;
        }
        unsigned long long o;
        o = __shfl_xor_sync(0xFFFFFFFFu, m0, 1); m0 = (o < m0) ? o : m0;
        o = __shfl_xor_sync(0xFFFFFFFFu, m0, 2); m0 = (o < m0) ? o : m0;
        o = __shfl_xor_sync(0xFFFFFFFFu, m1, 1); m1 = (o < m1) ? o : m1;
        o = __shfl_xor_sync(0xFFFFFFFFu, m1, 2); m1 = (o < m1) ? o : m1;
        if (t4 == 0) {
            red[r0][warp_n] = m0;
            red[r1][warp_n] = m1;
        }
    }
    __syncthreads();

    if (tid < TILE_M) {
        unsigned long long best = red[tid][0];
#pragma unroll
        for (int i = 1; i < 4; i++) {
            unsigned long long v = red[tid][i];
            best = (v < best) ? v : best;
        }
        g_blkmin[((size_t)(bi + tid) * H + h) * NBLK + blockIdx.y] = best;
    }
}

// ---------------------------------------------------------------------------
// Re-rank: block-min prune, then exact fp32 re-rank of surviving candidates.
// ---------------------------------------------------------------------------
__global__ __launch_bounds__(256)
void rerank_kernel(const float* __restrict__ x, const float* __restrict__ cb) {
    const int bh = blockIdx.x;
    const int b = bh >> 2;     // H = 4
    const int h = bh & 3;
    const int tid = threadIdx.x;

    __shared__ float xs[DHEAD];
    __shared__ unsigned long long sbm[NBLK];
    __shared__ unsigned long long best;
    __shared__ float s_thr;

    if (tid == 0) best = 0xFFFFFFFFFFFFFFFFull;
    xs[tid] = x[(size_t)b * DFULL + h * DHEAD + tid];

    const unsigned long long* bm = g_blkmin + (size_t)bh * NBLK;
    if (tid < NBLK) sbm[tid] = bm[tid];
    __syncthreads();

    if (tid < 32) {
        unsigned long long m = sbm[tid];
        unsigned long long v = sbm[tid + 32];
        m = (v < m) ? v : m;
#pragma unroll
        for (int o = 16; o; o >>= 1) {
            v = __shfl_xor_sync(0xFFFFFFFFu, m, o);
            m = (v < m) ? v : m;
        }
        if (tid == 0) s_thr = key_float((uint32_t)(m >> 32)) + MARGIN;
    }
    __syncthreads();
    const float thr = s_thr;

    // scan only blocks whose min is within margin
    for (int j = 0; j < NBLK; j++) {
        if (key_float((uint32_t)(sbm[j] >> 32)) > thr) continue;
        // threads 0-127 scan the 128 codes of this block
        if (tid < TILE_N) {
            int code = j * TILE_N + tid;
            float dv = __half2float(g_distH[(size_t)bh * KCODES + code]);
            if (dv <= thr) {
                const float* e = cb + ((size_t)h * KCODES + code) * DHEAD;
                float s0 = 0.f, s1 = 0.f, s2 = 0.f, s3 = 0.f;
#pragma unroll 8
                for (int d = 0; d < DHEAD; d += 4) {
                    s0 = fmaf(xs[d + 0], e[d + 0], s0);
                    s1 = fmaf(xs[d + 1], e[d + 1], s1);
                    s2 = fmaf(xs[d + 2], e[d + 2], s2);
                    s3 = fmaf(xs[d + 3], e[d + 3], s3);
                }
                float dot = (s0 + s1) + (s2 + s3);
                float de = fmaf(-2.f, dot, g_e2[h * KCODES + code]);
                unsigned long long key =
                    ((unsigned long long)float_key(de) << 32) | (unsigned)code;
                atomicMin(&best, key);
            }
        }
    }
    __syncthreads();
    if (tid == 0) g_code[bh] = (unsigned)(best & 0xFFFFFFFFu);
}

// ---------------------------------------------------------------------------
__global__ void finalize_kernel(const float* __restrict__ x, const float* __restrict__ cb,
                                float* __restrict__ loss, float* __restrict__ quant,
                                float* __restrict__ codes_out) {
    const int b = blockIdx.x;
    const int tid = threadIdx.x;
    __shared__ float sred[256];

    float partial = 0.f;
#pragma unroll
    for (int h = 0; h < H; h++) {
        unsigned code = g_code[b * H + h];
        if (tid == 0) codes_out[(size_t)b * H + h] = (float)code;
        float qv = cb[((size_t)h * KCODES + code) * DHEAD + tid];
        float xv = x[(size_t)b * DFULL + (size_t)h * DHEAD + tid];
        quant[(size_t)b * DFULL + (size_t)h * DHEAD + tid] = qv;
        float d = qv - xv;
        partial = fmaf(d, d, partial);
    }
    sred[tid] = partial;
    __syncthreads();
#pragma unroll
    for (int s = 128; s > 0; s >>= 1) {
        if (tid < s) sred[tid] += sred[tid + s];
        __syncthreads();
    }
    if (tid == 0) loss[b] = 0.25f * sred[0] * (1.0f / (float)DHEAD);
}

// ---------------------------------------------------------------------------
extern "C" void kernel_launch(void* const* d_in, const int* in_sizes, int n_in,
                              void* d_out, int out_size) {
    const float* x  = (const float*)d_in[0];
    const float* cb = (const float*)d_in[1];
    float* out = (float*)d_out;

    float* loss  = out;
    float* quant = out + BATCH;
    float* codes = out + BATCH + (size_t)BATCH * DFULL;

    __nv_bfloat16 *xb, *cbb;
    cudaGetSymbolAddress((void**)&xb, g_xb);
    cudaGetSymbolAddress((void**)&cbb, g_cbb);

    e2_kernel<<<(H * KCODES) / 8, 256>>>(cb);

    const int n8 = BATCH * DFULL / 8;
    cvt_kernel<<<(n8 + 255) / 256, 256>>>(x, xb, n8);
    cvt_kernel<<<(n8 + 255) / 256, 256>>>(cb, cbb, n8);

    dim3 grid(BATCH / TILE_M, KCODES / TILE_N, H);
    dist_kernel<<<grid, 256>>>();

    rerank_kernel<<<BATCH * H, 256>>>(x, cb);

    finalize_kernel<<<BATCH, 256>>>(x, cb, loss, quant, codes);
}

// round 9
// speedup vs baseline: 2.4806x; 1.2034x over previous
#include <cuda_runtime.h>
#include <cuda_bf16.h>
#include <cuda_fp16.h>
#include <cstdint>

#define H 4
#define KCODES 8192
#define DFULL 1024
#define DHEAD 256
#define BATCH 8192

#define TILE_M 128
#define TILE_N 128
#define NBLK (KCODES / TILE_N)   // 64
#define KC 32
#define NCHUNK (DHEAD / KC)      // 8
#define LD2 40
#define MARGIN 4.0f

// Scratch
__device__ float g_e2[H * KCODES];
__device__ __nv_bfloat16 g_xb[(size_t)BATCH * DFULL];
__device__ __nv_bfloat16 g_cbb[(size_t)H * KCODES * DHEAD];
__device__ __half g_distH[(size_t)BATCH * H * KCODES];
__device__ unsigned long long g_blkmin[(size_t)BATCH * H * NBLK];
__device__ unsigned g_code[BATCH * H];

__device__ __forceinline__ uint32_t float_key(float f) {
    unsigned ub = __float_as_uint(f);
    return (ub & 0x80000000u) ? ~ub : (ub | 0x80000000u);
}
__device__ __forceinline__ float key_float(uint32_t k) {
    unsigned ub = (k & 0x80000000u) ? (k & 0x7FFFFFFFu) : ~k;
    return __uint_as_float(ub);
}

#define MMA_BF16(c, a, b0, b1) \
    asm volatile("mma.sync.aligned.m16n8k16.row.col.f32.bf16.bf16.f32 " \
        "{%0,%1,%2,%3}, {%4,%5,%6,%7}, {%8,%9}, {%0,%1,%2,%3};" \
        : "+f"((c)[0]), "+f"((c)[1]), "+f"((c)[2]), "+f"((c)[3]) \
        : "r"((a)[0]), "r"((a)[1]), "r"((a)[2]), "r"((a)[3]), \
          "r"(b0), "r"(b1))

#define LDSM_X4(r0, r1, r2, r3, addr) \
    asm volatile("ldmatrix.sync.aligned.m8n8.x4.shared.b16 {%0,%1,%2,%3}, [%4];" \
        : "=r"(r0), "=r"(r1), "=r"(r2), "=r"(r3) : "r"(addr))
#define LDSM_X2(r0, r1, addr) \
    asm volatile("ldmatrix.sync.aligned.m8n8.x2.shared.b16 {%0,%1}, [%2];" \
        : "=r"(r0), "=r"(r1) : "r"(addr))

#define CP_ASYNC16(dst, src) \
    asm volatile("cp.async.cg.shared.global [%0], [%1], 16;" :: "r"(dst), "l"(src))
#define CP_COMMIT() asm volatile("cp.async.commit_group;" ::: "memory")
#define CP_WAIT(n)  asm volatile("cp.async.wait_group %0;" :: "n"(n) : "memory")

// ---------------------------------------------------------------------------
// Fused: e2[h,k] + bf16 conversion of codebook. Warp per code row.
// ---------------------------------------------------------------------------
__global__ void e2cvt_kernel(const float* __restrict__ cb) {
    int warp = (blockIdx.x * blockDim.x + threadIdx.x) >> 5;
    int lane = threadIdx.x & 31;
    if (warp >= H * KCODES) return;
    const float4* p = (const float4*)(cb + (size_t)warp * DHEAD);
    float4 v0 = p[lane * 2];
    float4 v1 = p[lane * 2 + 1];
    float s = v0.x * v0.x + v0.y * v0.y + v0.z * v0.z + v0.w * v0.w
            + v1.x * v1.x + v1.y * v1.y + v1.z * v1.z + v1.w * v1.w;
#pragma unroll
    for (int o = 16; o; o >>= 1) s += __shfl_xor_sync(0xFFFFFFFFu, s, o);
    if (lane == 0) g_e2[warp] = s;

    __nv_bfloat162 ob[4];
    ob[0] = __nv_bfloat162(__float2bfloat16_rn(v0.x), __float2bfloat16_rn(v0.y));
    ob[1] = __nv_bfloat162(__float2bfloat16_rn(v0.z), __float2bfloat16_rn(v0.w));
    ob[2] = __nv_bfloat162(__float2bfloat16_rn(v1.x), __float2bfloat16_rn(v1.y));
    ob[3] = __nv_bfloat162(__float2bfloat16_rn(v1.z), __float2bfloat16_rn(v1.w));
    ((uint4*)(g_cbb + (size_t)warp * DHEAD))[lane] = *(uint4*)ob;
}

__global__ void cvt_kernel(const float* __restrict__ src, __nv_bfloat16* __restrict__ dst, int n8) {
    int i = blockIdx.x * blockDim.x + threadIdx.x;
    if (i >= n8) return;
    float4 a = ((const float4*)src)[2 * i];
    float4 b = ((const float4*)src)[2 * i + 1];
    __nv_bfloat162 o[4];
    o[0] = __nv_bfloat162(__float2bfloat16_rn(a.x), __float2bfloat16_rn(a.y));
    o[1] = __nv_bfloat162(__float2bfloat16_rn(a.z), __float2bfloat16_rn(a.w));
    o[2] = __nv_bfloat162(__float2bfloat16_rn(b.x), __float2bfloat16_rn(b.y));
    o[3] = __nv_bfloat162(__float2bfloat16_rn(b.z), __float2bfloat16_rn(b.w));
    ((uint4*)dst)[i] = *(uint4*)o;
}

// ---------------------------------------------------------------------------
// 1-pass BF16 GEMM (ldmatrix fragments) storing fp16 dists + block mins.
// ---------------------------------------------------------------------------
__global__ __launch_bounds__(256, 2)
void dist_kernel() {
    __shared__ __half As[2][TILE_M * LD2];
    __shared__ __half Bs[2][TILE_N * LD2];
    __shared__ float e2s[TILE_N];
    __shared__ unsigned long long red[TILE_M][4];

    const int tid = threadIdx.x;
    const int lane = tid & 31;
    const int wid = tid >> 5;
    const int warp_m = wid & 1;
    const int warp_n = wid >> 1;
    const int g  = lane >> 2;
    const int t4 = lane & 3;

    const int h  = blockIdx.z;
    const int bi = blockIdx.x * TILE_M;
    const int kj = blockIdx.y * TILE_N;

    if (tid < TILE_N) e2s[tid] = g_e2[h * KCODES + kj + tid];

    const __nv_bfloat16* xg = g_xb  + (size_t)bi * DFULL + (size_t)h * DHEAD;
    const __nv_bfloat16* eg = g_cbb + ((size_t)h * KCODES + kj) * DHEAD;

    const uint32_t sA[2] = {
        (uint32_t)__cvta_generic_to_shared(&As[0][0]),
        (uint32_t)__cvta_generic_to_shared(&As[1][0])};
    const uint32_t sB[2] = {
        (uint32_t)__cvta_generic_to_shared(&Bs[0][0]),
        (uint32_t)__cvta_generic_to_shared(&Bs[1][0])};

    // ldmatrix per-lane address components
    const int lr  = lane & 7;
    const int seg = lane >> 3;                    // 0..3
    const int a_row = ((seg & 1) ? 8 : 0) + lr;   // within 16-row tile
    const int a_k   = (seg & 2) ? 8 : 0;
    const int b_row = lr;
    const int b_k   = (seg & 1) ? 8 : 0;          // only lanes 0-15 used by x2

    float acc[4][4][4];
#pragma unroll
    for (int mt = 0; mt < 4; mt++)
#pragma unroll
        for (int nt = 0; nt < 4; nt++)
#pragma unroll
            for (int r = 0; r < 4; r++) acc[mt][nt][r] = 0.f;

#define COPY_CHUNK(buf, ck) do { \
        _Pragma("unroll") \
        for (int i = 0; i < 2; i++) { \
            int idx = tid + 256 * i; \
            int r = idx >> 2, s8 = idx & 3; \
            uint32_t off = (uint32_t)(r * LD2 + s8 * 8) * 2u; \
            CP_ASYNC16(sA[buf] + off, xg + (size_t)r * DFULL + (ck) * KC + s8 * 8); \
            CP_ASYNC16(sB[buf] + off, eg + (size_t)r * DHEAD + (ck) * KC + s8 * 8); \
        } \
    } while (0)

    COPY_CHUNK(0, 0);
    CP_COMMIT();

#pragma unroll 1
    for (int ck = 0; ck < NCHUNK; ck++) {
        if (ck + 1 < NCHUNK) {
            COPY_CHUNK((ck + 1) & 1, ck + 1);
            CP_COMMIT();
            CP_WAIT(1);
        } else {
            CP_WAIT(0);
        }
        __syncthreads();

        const uint32_t sAc = sA[ck & 1];
        const uint32_t sBc = sB[ck & 1];

#pragma unroll
        for (int ks = 0; ks < 2; ks++) {
            const int k0 = ks * 16;
            uint32_t a[4][4], b[4][2];
#pragma unroll
            for (int mt = 0; mt < 4; mt++) {
                uint32_t addr = sAc +
                    (uint32_t)(((warp_m * 64 + mt * 16 + a_row) * LD2 + k0 + a_k) * 2);
                LDSM_X4(a[mt][0], a[mt][1], a[mt][2], a[mt][3], addr);
            }
#pragma unroll
            for (int nt = 0; nt < 4; nt++) {
                uint32_t addr = sBc +
                    (uint32_t)(((warp_n * 32 + nt * 8 + b_row) * LD2 + k0 + b_k) * 2);
                LDSM_X2(b[nt][0], b[nt][1], addr);
            }
#pragma unroll
            for (int nt = 0; nt < 4; nt++)
#pragma unroll
                for (int mt = 0; mt < 4; mt++)
                    MMA_BF16(acc[mt][nt], a[mt], b[nt][0], b[nt][1]);
        }
        __syncthreads();
    }

    // ---- epilogue: dist = e2 - 2*acc; fp16 store + per-row block min ----
#pragma unroll
    for (int mt = 0; mt < 4; mt++) {
        int r0 = warp_m * 64 + mt * 16 + g;
        int r1 = r0 + 8;
        size_t base0 = ((size_t)(bi + r0) * H + h) * KCODES + kj;
        size_t base1 = ((size_t)(bi + r1) * H + h) * KCODES + kj;
        unsigned long long m0 = 0xFFFFFFFFFFFFFFFFull;
        unsigned long long m1 = 0xFFFFFFFFFFFFFFFFull;
#pragma unroll
        for (int nt = 0; nt < 4; nt++) {
            int c0 = warp_n * 32 + nt * 8 + 2 * t4;
            float d00 = fmaf(-2.f, acc[mt][nt][0], e2s[c0]);
            float d01 = fmaf(-2.f, acc[mt][nt][1], e2s[c0 + 1]);
            float d10 = fmaf(-2.f, acc[mt][nt][2], e2s[c0]);
            float d11 = fmaf(-2.f, acc[mt][nt][3], e2s[c0 + 1]);
            *(__half2*)&g_distH[base0 + c0] = __floats2half2_rn(d00, d01);
            *(__half2*)&g_distH[base1 + c0] = __floats2half2_rn(d10, d11);
            unsigned long long k00 = ((unsigned long long)float_key(d00) << 32) | (unsigned)(kj + c0);
            unsigned long long k01 = ((unsigned long long)float_key(d01) << 32) | (unsigned)(kj + c0 + 1);
            unsigned long long k10 = ((unsigned long long)float_key(d10) << 32) | (unsigned)(kj + c0);
            unsigned long long k11 = ((unsigned long long)float_key(d11) << 32) | (unsigned)(kj + c0 + 1);
            m0 = (k00 < m0) ? k00 : m0;  m0 = (k01 < m0) ? k01 : m0;
            m1 = (k10 < m1) ? k10 : m1;  m1 = (k11 < m1) ? k11 : m1;
        }
        unsigned long long o;
        o = __shfl_xor_sync(0xFFFFFFFFu, m0, 1); m0 = (o < m0) ? o : m0;
        o = __shfl_xor_sync(0xFFFFFFFFu, m0, 2); m0 = (o < m0) ? o : m0;
        o = __shfl_xor_sync(0xFFFFFFFFu, m1, 1); m1 = (o < m1) ? o : m1;
        o = __shfl_xor_sync(0xFFFFFFFFu, m1, 2); m1 = (o < m1) ? o : m1;
        if (t4 == 0) {
            red[r0][warp_n] = m0;
            red[r1][warp_n] = m1;
        }
    }
    __syncthreads();

    if (tid < TILE_M) {
        unsigned long long best = red[tid][0];
#pragma unroll
        for (int i = 1; i < 4; i++) {
            unsigned long long v = red[tid][i];
            best = (v < best) ? v : best;
        }
        g_blkmin[((size_t)(bi + tid) * H + h) * NBLK + blockIdx.y] = best;
    }
}

// ---------------------------------------------------------------------------
// Re-rank: block-min prune; candidates evaluated cooperatively (256 threads).
// ---------------------------------------------------------------------------
__global__ __launch_bounds__(256)
void rerank_kernel(const float* __restrict__ x, const float* __restrict__ cb) {
    const int bh = blockIdx.x;
    const int b = bh >> 2;
    const int h = bh & 3;
    const int tid = threadIdx.x;
    const int lane = tid & 31;
    const int wid = tid >> 5;

    __shared__ float xs[DHEAD];
    __shared__ unsigned long long sbm[NBLK];
    __shared__ int cand[64];
    __shared__ int ncand;
    __shared__ float s_thr;
    __shared__ float wpart[8];
    __shared__ unsigned long long best;

    if (tid == 0) { ncand = 0; best = 0xFFFFFFFFFFFFFFFFull; }
    xs[tid] = x[(size_t)b * DFULL + h * DHEAD + tid];
    if (tid < NBLK) sbm[tid] = g_blkmin[(size_t)bh * NBLK + tid];
    __syncthreads();

    if (tid < 32) {
        unsigned long long m = sbm[tid];
        unsigned long long v = sbm[tid + 32];
        m = (v < m) ? v : m;
#pragma unroll
        for (int o = 16; o; o >>= 1) {
            v = __shfl_xor_sync(0xFFFFFFFFu, m, o);
            m = (v < m) ? v : m;
        }
        if (tid == 0) s_thr = key_float((uint32_t)(m >> 32)) + MARGIN;
    }
    __syncthreads();
    const float thr = s_thr;

    // candidate collection over surviving blocks
    for (int j = 0; j < NBLK; j++) {
        if (key_float((uint32_t)(sbm[j] >> 32)) > thr) continue;
        if (tid < TILE_N) {
            int code = j * TILE_N + tid;
            float dv = __half2float(g_distH[(size_t)bh * KCODES + code]);
            if (dv <= thr) {
                int s = atomicAdd(&ncand, 1);
                if (s < 64) cand[s] = code;
            }
        }
    }
    __syncthreads();

    const int n = (ncand < 64) ? ncand : 64;
    for (int c = 0; c < n; c++) {
        int code = cand[c];
        float p = xs[tid] * cb[((size_t)h * KCODES + code) * DHEAD + tid];
#pragma unroll
        for (int o = 16; o; o >>= 1) p += __shfl_xor_sync(0xFFFFFFFFu, p, o);
        if (lane == 0) wpart[wid] = p;
        __syncthreads();
        if (tid == 0) {
            float dot = 0.f;
#pragma unroll
            for (int w = 0; w < 8; w++) dot += wpart[w];
            float de = fmaf(-2.f, dot, g_e2[h * KCODES + code]);
            unsigned long long key =
                ((unsigned long long)float_key(de) << 32) | (unsigned)code;
            best = (key < best) ? key : best;
        }
        __syncthreads();
    }
    if (tid == 0) g_code[bh] = (unsigned)(best & 0xFFFFFFFFu);
}

// ---------------------------------------------------------------------------
__global__ void finalize_kernel(const float* __restrict__ x, const float* __restrict__ cb,
                                float* __restrict__ loss, float* __restrict__ quant,
                                float* __restrict__ codes_out) {
    const int b = blockIdx.x;
    const int tid = threadIdx.x;
    __shared__ float sred[256];

    float partial = 0.f;
#pragma unroll
    for (int h = 0; h < H; h++) {
        unsigned code = g_code[b * H + h];
        if (tid == 0) codes_out[(size_t)b * H + h] = (float)code;
        float qv = cb[((size_t)h * KCODES + code) * DHEAD + tid];
        float xv = x[(size_t)b * DFULL + (size_t)h * DHEAD + tid];
        quant[(size_t)b * DFULL + (size_t)h * DHEAD + tid] = qv;
        float d = qv - xv;
        partial = fmaf(d, d, partial);
    }
    sred[tid] = partial;
    __syncthreads();
#pragma unroll
    for (int s = 128; s > 0; s >>= 1) {
        if (tid < s) sred[tid] += sred[tid + s];
        __syncthreads();
    }
    if (tid == 0) loss[b] = 0.25f * sred[0] * (1.0f / (float)DHEAD);
}

// ---------------------------------------------------------------------------
extern "C" void kernel_launch(void* const* d_in, const int* in_sizes, int n_in,
                              void* d_out, int out_size) {
    const float* x  = (const float*)d_in[0];
    const float* cb = (const float*)d_in[1];
    float* out = (float*)d_out;

    float* loss  = out;
    float* quant = out + BATCH;
    float* codes = out + BATCH + (size_t)BATCH * DFULL;

    __nv_bfloat16* xb;
    cudaGetSymbolAddress((void**)&xb, g_xb);

    e2cvt_kernel<<<(H * KCODES) / 8, 256>>>(cb);

    const int n8 = BATCH * DFULL / 8;
    cvt_kernel<<<(n8 + 255) / 256, 256>>>(x, xb, n8);

    dim3 grid(BATCH / TILE_M, KCODES / TILE_N, H);
    dist_kernel<<<grid, 256>>>();

    rerank_kernel<<<BATCH * H, 256>>>(x, cb);

    finalize_kernel<<<BATCH, 256>>>(x, cb, loss, quant, codes);
}

// round 10
// speedup vs baseline: 3.2683x; 1.3175x over previous
#include <cuda_runtime.h>
#include <cuda_bf16.h>
#include <cuda_fp16.h>
#include <cstdint>

#define H 4
#define KCODES 8192
#define DFULL 1024
#define DHEAD 256
#define BATCH 8192

#define TILE_M 128
#define TILE_N 128
#define NBLK (KCODES / TILE_N)   // 64
#define KC 32
#define NCHUNK (DHEAD / KC)      // 8
#define LD2 40
#define MARGIN 4.0f
#define MAXCAND 256

// Scratch
__device__ float g_e2[H * KCODES];
__device__ __nv_bfloat16 g_xb[(size_t)BATCH * DFULL];
__device__ __nv_bfloat16 g_cbb[(size_t)H * KCODES * DHEAD];
__device__ __half g_distH[(size_t)BATCH * H * KCODES];
__device__ unsigned long long g_blkmin[(size_t)BATCH * H * NBLK];

__device__ __forceinline__ uint32_t float_key(float f) {
    unsigned ub = __float_as_uint(f);
    return (ub & 0x80000000u) ? ~ub : (ub | 0x80000000u);
}
__device__ __forceinline__ float key_float(uint32_t k) {
    unsigned ub = (k & 0x80000000u) ? (k & 0x7FFFFFFFu) : ~k;
    return __uint_as_float(ub);
}

#define MMA_BF16(c, a, b0, b1) \
    asm volatile("mma.sync.aligned.m16n8k16.row.col.f32.bf16.bf16.f32 " \
        "{%0,%1,%2,%3}, {%4,%5,%6,%7}, {%8,%9}, {%0,%1,%2,%3};" \
        : "+f"((c)[0]), "+f"((c)[1]), "+f"((c)[2]), "+f"((c)[3]) \
        : "r"((a)[0]), "r"((a)[1]), "r"((a)[2]), "r"((a)[3]), \
          "r"(b0), "r"(b1))

#define LDSM_X4(r0, r1, r2, r3, addr) \
    asm volatile("ldmatrix.sync.aligned.m8n8.x4.shared.b16 {%0,%1,%2,%3}, [%4];" \
        : "=r"(r0), "=r"(r1), "=r"(r2), "=r"(r3) : "r"(addr))
#define LDSM_X2(r0, r1, addr) \
    asm volatile("ldmatrix.sync.aligned.m8n8.x2.shared.b16 {%0,%1}, [%2];" \
        : "=r"(r0), "=r"(r1) : "r"(addr))

#define CP_ASYNC16(dst, src) \
    asm volatile("cp.async.cg.shared.global [%0], [%1], 16;" :: "r"(dst), "l"(src))
#define CP_COMMIT() asm volatile("cp.async.commit_group;" ::: "memory")
#define CP_WAIT(n)  asm volatile("cp.async.wait_group %0;" :: "n"(n) : "memory")

// ---------------------------------------------------------------------------
// Fused: e2[h,k] + bf16 conversion of codebook. Warp per code row.
// ---------------------------------------------------------------------------
__global__ void e2cvt_kernel(const float* __restrict__ cb) {
    int warp = (blockIdx.x * blockDim.x + threadIdx.x) >> 5;
    int lane = threadIdx.x & 31;
    if (warp >= H * KCODES) return;
    const float4* p = (const float4*)(cb + (size_t)warp * DHEAD);
    float4 v0 = p[lane * 2];
    float4 v1 = p[lane * 2 + 1];
    float s = v0.x * v0.x + v0.y * v0.y + v0.z * v0.z + v0.w * v0.w
            + v1.x * v1.x + v1.y * v1.y + v1.z * v1.z + v1.w * v1.w;
#pragma unroll
    for (int o = 16; o; o >>= 1) s += __shfl_xor_sync(0xFFFFFFFFu, s, o);
    if (lane == 0) g_e2[warp] = s;

    __nv_bfloat162 ob[4];
    ob[0] = __nv_bfloat162(__float2bfloat16_rn(v0.x), __float2bfloat16_rn(v0.y));
    ob[1] = __nv_bfloat162(__float2bfloat16_rn(v0.z), __float2bfloat16_rn(v0.w));
    ob[2] = __nv_bfloat162(__float2bfloat16_rn(v1.x), __float2bfloat16_rn(v1.y));
    ob[3] = __nv_bfloat162(__float2bfloat16_rn(v1.z), __float2bfloat16_rn(v1.w));
    ((uint4*)(g_cbb + (size_t)warp * DHEAD))[lane] = *(uint4*)ob;
}

__global__ void cvt_kernel(const float* __restrict__ src, __nv_bfloat16* __restrict__ dst, int n8) {
    int i = blockIdx.x * blockDim.x + threadIdx.x;
    if (i >= n8) return;
    float4 a = ((const float4*)src)[2 * i];
    float4 b = ((const float4*)src)[2 * i + 1];
    __nv_bfloat162 o[4];
    o[0] = __nv_bfloat162(__float2bfloat16_rn(a.x), __float2bfloat16_rn(a.y));
    o[1] = __nv_bfloat162(__float2bfloat16_rn(a.z), __float2bfloat16_rn(a.w));
    o[2] = __nv_bfloat162(__float2bfloat16_rn(b.x), __float2bfloat16_rn(b.y));
    o[3] = __nv_bfloat162(__float2bfloat16_rn(b.z), __float2bfloat16_rn(b.w));
    ((uint4*)dst)[i] = *(uint4*)o;
}

// ---------------------------------------------------------------------------
// 1-pass BF16 GEMM (ldmatrix fragments) storing fp16 dists + block mins.
// ---------------------------------------------------------------------------
__global__ __launch_bounds__(256, 2)
void dist_kernel() {
    __shared__ __half As[2][TILE_M * LD2];
    __shared__ __half Bs[2][TILE_N * LD2];
    __shared__ float e2s[TILE_N];
    __shared__ unsigned long long red[TILE_M][4];

    const int tid = threadIdx.x;
    const int lane = tid & 31;
    const int wid = tid >> 5;
    const int warp_m = wid & 1;
    const int warp_n = wid >> 1;
    const int g  = lane >> 2;
    const int t4 = lane & 3;

    const int h  = blockIdx.z;
    const int bi = blockIdx.x * TILE_M;
    const int kj = blockIdx.y * TILE_N;

    if (tid < TILE_N) e2s[tid] = g_e2[h * KCODES + kj + tid];

    const __nv_bfloat16* xg = g_xb  + (size_t)bi * DFULL + (size_t)h * DHEAD;
    const __nv_bfloat16* eg = g_cbb + ((size_t)h * KCODES + kj) * DHEAD;

    const uint32_t sA[2] = {
        (uint32_t)__cvta_generic_to_shared(&As[0][0]),
        (uint32_t)__cvta_generic_to_shared(&As[1][0])};
    const uint32_t sB[2] = {
        (uint32_t)__cvta_generic_to_shared(&Bs[0][0]),
        (uint32_t)__cvta_generic_to_shared(&Bs[1][0])};

    const int lr  = lane & 7;
    const int seg = lane >> 3;
    const int a_row = ((seg & 1) ? 8 : 0) + lr;
    const int a_k   = (seg & 2) ? 8 : 0;
    const int b_row = lr;
    const int b_k   = (seg & 1) ? 8 : 0;

    float acc[4][4][4];
#pragma unroll
    for (int mt = 0; mt < 4; mt++)
#pragma unroll
        for (int nt = 0; nt < 4; nt++)
#pragma unroll
            for (int r = 0; r < 4; r++) acc[mt][nt][r] = 0.f;

#define COPY_CHUNK(buf, ck) do { \
        _Pragma("unroll") \
        for (int i = 0; i < 2; i++) { \
            int idx = tid + 256 * i; \
            int r = idx >> 2, s8 = idx & 3; \
            uint32_t off = (uint32_t)(r * LD2 + s8 * 8) * 2u; \
            CP_ASYNC16(sA[buf] + off, xg + (size_t)r * DFULL + (ck) * KC + s8 * 8); \
            CP_ASYNC16(sB[buf] + off, eg + (size_t)r * DHEAD + (ck) * KC + s8 * 8); \
        } \
    } while (0)

    COPY_CHUNK(0, 0);
    CP_COMMIT();

#pragma unroll 1
    for (int ck = 0; ck < NCHUNK; ck++) {
        if (ck + 1 < NCHUNK) {
            COPY_CHUNK((ck + 1) & 1, ck + 1);
            CP_COMMIT();
            CP_WAIT(1);
        } else {
            CP_WAIT(0);
        }
        __syncthreads();

        const uint32_t sAc = sA[ck & 1];
        const uint32_t sBc = sB[ck & 1];

#pragma unroll
        for (int ks = 0; ks < 2; ks++) {
            const int k0 = ks * 16;
            uint32_t a[4][4], b[4][2];
#pragma unroll
            for (int mt = 0; mt < 4; mt++) {
                uint32_t addr = sAc +
                    (uint32_t)(((warp_m * 64 + mt * 16 + a_row) * LD2 + k0 + a_k) * 2);
                LDSM_X4(a[mt][0], a[mt][1], a[mt][2], a[mt][3], addr);
            }
#pragma unroll
            for (int nt = 0; nt < 4; nt++) {
                uint32_t addr = sBc +
                    (uint32_t)(((warp_n * 32 + nt * 8 + b_row) * LD2 + k0 + b_k) * 2);
                LDSM_X2(b[nt][0], b[nt][1], addr);
            }
#pragma unroll
            for (int nt = 0; nt < 4; nt++)
#pragma unroll
                for (int mt = 0; mt < 4; mt++)
                    MMA_BF16(acc[mt][nt], a[mt], b[nt][0], b[nt][1]);
        }
        __syncthreads();
    }

    // ---- epilogue: dist = e2 - 2*acc; fp16 store + per-row block min ----
#pragma unroll
    for (int mt = 0; mt < 4; mt++) {
        int r0 = warp_m * 64 + mt * 16 + g;
        int r1 = r0 + 8;
        size_t base0 = ((size_t)(bi + r0) * H + h) * KCODES + kj;
        size_t base1 = ((size_t)(bi + r1) * H + h) * KCODES + kj;
        unsigned long long m0 = 0xFFFFFFFFFFFFFFFFull;
        unsigned long long m1 = 0xFFFFFFFFFFFFFFFFull;
#pragma unroll
        for (int nt = 0; nt < 4; nt++) {
            int c0 = warp_n * 32 + nt * 8 + 2 * t4;
            float d00 = fmaf(-2.f, acc[mt][nt][0], e2s[c0]);
            float d01 = fmaf(-2.f, acc[mt][nt][1], e2s[c0 + 1]);
            float d10 = fmaf(-2.f, acc[mt][nt][2], e2s[c0]);
            float d11 = fmaf(-2.f, acc[mt][nt][3], e2s[c0 + 1]);
            *(__half2*)&g_distH[base0 + c0] = __floats2half2_rn(d00, d01);
            *(__half2*)&g_distH[base1 + c0] = __floats2half2_rn(d10, d11);
            unsigned long long k00 = ((unsigned long long)float_key(d00) << 32) | (unsigned)(kj + c0);
            unsigned long long k01 = ((unsigned long long)float_key(d01) << 32) | (unsigned)(kj + c0 + 1);
            unsigned long long k10 = ((unsigned long long)float_key(d10) << 32) | (unsigned)(kj + c0);
            unsigned long long k11 = ((unsigned long long)float_key(d11) << 32) | (unsigned)(kj + c0 + 1);
            m0 = (k00 < m0) ? k00 : m0;  m0 = (k01 < m0) ? k01 : m0;
            m1 = (k10 < m1) ? k10 : m1;  m1 = (k11 < m1) ? k11 : m1;
        }
        unsigned long long o;
        o = __shfl_xor_sync(0xFFFFFFFFu, m0, 1); m0 = (o < m0) ? o : m0;
        o = __shfl_xor_sync(0xFFFFFFFFu, m0, 2); m0 = (o < m0) ? o : m0;
        o = __shfl_xor_sync(0xFFFFFFFFu, m1, 1); m1 = (o < m1) ? o : m1;
        o = __shfl_xor_sync(0xFFFFFFFFu, m1, 2); m1 = (o < m1) ? o : m1;
        if (t4 == 0) {
            red[r0][warp_n] = m0;
            red[r1][warp_n] = m1;
        }
    }
    __syncthreads();

    if (tid < TILE_M) {
        unsigned long long best = red[tid][0];
#pragma unroll
        for (int i = 1; i < 4; i++) {
            unsigned long long v = red[tid][i];
            best = (v < best) ? v : best;
        }
        g_blkmin[((size_t)(bi + tid) * H + h) * NBLK + blockIdx.y] = best;
    }
}

// ---------------------------------------------------------------------------
// Fused re-rank + finalize: one block per batch row (all 4 heads).
// ---------------------------------------------------------------------------
__global__ __launch_bounds__(256)
void rerank_finalize_kernel(const float* __restrict__ x, const float* __restrict__ cb,
                            float* __restrict__ loss, float* __restrict__ quant,
                            float* __restrict__ codes_out) {
    const int b = blockIdx.x;
    const int tid = threadIdx.x;
    const int lane = tid & 31;
    const int wid = tid >> 5;

    __shared__ float xs[DFULL];
    __shared__ unsigned long long sbm[H * NBLK];   // 256
    __shared__ float thrsh[H];
    __shared__ unsigned long long bestk[H];
    __shared__ short2 plist[H * NBLK];
    __shared__ int npairs;
    __shared__ int cand[MAXCAND];                  // (h<<16)|code
    __shared__ int ncand;
    __shared__ float sred[256];

    ((float4*)xs)[tid] = ((const float4*)(x + (size_t)b * DFULL))[tid];
    sbm[tid] = g_blkmin[(size_t)b * (H * NBLK) + tid];
    if (tid < H) bestk[tid] = 0xFFFFFFFFFFFFFFFFull;
    if (tid == 0) { npairs = 0; ncand = 0; }
    __syncthreads();

    // per-head approx min (warp per head)
    if (wid < H) {
        unsigned long long m = sbm[wid * NBLK + lane];
        unsigned long long v = sbm[wid * NBLK + 32 + lane];
        m = (v < m) ? v : m;
#pragma unroll
        for (int o = 16; o; o >>= 1) {
            v = __shfl_xor_sync(0xFFFFFFFFu, m, o);
            m = (v < m) ? v : m;
        }
        if (lane == 0) thrsh[wid] = key_float((uint32_t)(m >> 32)) + MARGIN;
    }
    __syncthreads();

    // surviving (h, blk) pairs — one thread per pair slot
    {
        int h = tid >> 6, blk = tid & 63;
        if (key_float((uint32_t)(sbm[tid] >> 32)) <= thrsh[h]) {
            int s = atomicAdd(&npairs, 1);
            plist[s] = make_short2((short)h, (short)blk);
        }
    }
    __syncthreads();

    // scan surviving blocks: one warp per pair, 4 fp16 dists per lane
    for (int p = wid; p < npairs; p += 8) {
        int h = plist[p].x, blk = plist[p].y;
        const float thr = thrsh[h];
        const __half* dp = g_distH + ((size_t)b * H + h) * KCODES + blk * TILE_N;
        uint2 rv = ((const uint2*)dp)[lane];
        __half2 q0 = *(__half2*)&rv.x;
        __half2 q1 = *(__half2*)&rv.y;
        float f[4] = {__low2float(q0), __high2float(q0), __low2float(q1), __high2float(q1)};
#pragma unroll
        for (int j = 0; j < 4; j++) {
            if (f[j] <= thr) {
                int s = atomicAdd(&ncand, 1);
                if (s < MAXCAND)
                    cand[s] = (h << 16) | (blk * TILE_N + lane * 4 + j);
            }
        }
    }
    __syncthreads();

    // exact fp32 re-rank: one warp per candidate, 8 dims per lane
    const int n = (ncand < MAXCAND) ? ncand : MAXCAND;
    for (int c = wid; c < n; c += 8) {
        int hc = cand[c] >> 16, code = cand[c] & 0xFFFF;
        const float4* e = (const float4*)(cb + ((size_t)hc * KCODES + code) * DHEAD);
        float4 e0 = e[lane * 2];
        float4 e1 = e[lane * 2 + 1];
        const float* xh = xs + hc * DHEAD + lane * 8;
        float s = 0.f;
        s = fmaf(e0.x, xh[0], s); s = fmaf(e0.y, xh[1], s);
        s = fmaf(e0.z, xh[2], s); s = fmaf(e0.w, xh[3], s);
        s = fmaf(e1.x, xh[4], s); s = fmaf(e1.y, xh[5], s);
        s = fmaf(e1.z, xh[6], s); s = fmaf(e1.w, xh[7], s);
#pragma unroll
        for (int o = 16; o; o >>= 1) s += __shfl_xor_sync(0xFFFFFFFFu, s, o);
        if (lane == 0) {
            float de = fmaf(-2.f, s, g_e2[hc * KCODES + code]);
            unsigned long long key =
                ((unsigned long long)float_key(de) << 32) | (unsigned)code;
            atomicMin(&bestk[hc], key);
        }
    }
    __syncthreads();

    // finalize: quant, codes, loss
    float partial = 0.f;
#pragma unroll
    for (int h = 0; h < H; h++) {
        unsigned code = (unsigned)(bestk[h] & 0xFFFFFFFFu);
        if (tid == 0) codes_out[(size_t)b * H + h] = (float)code;
        float qv = cb[((size_t)h * KCODES + code) * DHEAD + tid];
        float xv = xs[h * DHEAD + tid];
        quant[(size_t)b * DFULL + (size_t)h * DHEAD + tid] = qv;
        float d = qv - xv;
        partial = fmaf(d, d, partial);
    }
    sred[tid] = partial;
    __syncthreads();
#pragma unroll
    for (int s = 128; s > 0; s >>= 1) {
        if (tid < s) sred[tid] += sred[tid + s];
        __syncthreads();
    }
    if (tid == 0) loss[b] = 0.25f * sred[0] * (1.0f / (float)DHEAD);
}

// ---------------------------------------------------------------------------
extern "C" void kernel_launch(void* const* d_in, const int* in_sizes, int n_in,
                              void* d_out, int out_size) {
    const float* x  = (const float*)d_in[0];
    const float* cb = (const float*)d_in[1];
    float* out = (float*)d_out;

    float* loss  = out;
    float* quant = out + BATCH;
    float* codes = out + BATCH + (size_t)BATCH * DFULL;

    __nv_bfloat16* xb;
    cudaGetSymbolAddress((void**)&xb, g_xb);

    e2cvt_kernel<<<(H * KCODES) / 8, 256>>>(cb);

    const int n8 = BATCH * DFULL / 8;
    cvt_kernel<<<(n8 + 255) / 256, 256>>>(x, xb, n8);

    dim3 grid(BATCH / TILE_M, KCODES / TILE_N, H);
    dist_kernel<<<grid, 256>>>();

    rerank_finalize_kernel<<<BATCH, 256>>>(x, cb, loss, quant, codes);
}